// round 10
// baseline (speedup 1.0000x reference)
#include <cuda_runtime.h>
#include <cuda_fp16.h>
#include <cstdint>
#include <cstddef>

// ---------------------------------------------------------------------------
// ConvVAE2d via mma.sync fp16 GEMMs (baseline sm_103 PTX: cp.async + ldmatrix
// + mma.sync.m16n8k16; tcgen05 unavailable on this toolchain target).
// R9: dec1/dec2 use f16-accumulate HMMA (probe: rt 8 vs 16) with per-BK
// promotion into fp32 master accumulators; enc1/enc2 keep f32-acc HMMA.
// ---------------------------------------------------------------------------

#define TOK 16384
#define PD  768
#define HD  2048
#define L2D 512
#define LDIM 256

// ----------------------------- scratch -------------------------------------
__device__ __align__(256) __half g_p[TOK * PD];
__device__ __align__(256) __half g_he[TOK * HD];
__device__ __align__(256) float  g_ml[TOK * L2D];
__device__ __align__(256) __half g_mu[TOK * LDIM];
__device__ __align__(256) __half g_hd[TOK * HD];
__device__ __align__(256) __half g_w1t[HD * PD];
__device__ __align__(256) __half g_w2t[L2D * HD];
__device__ __align__(256) __half g_w3t[HD * LDIM];
__device__ __align__(256) __half g_w4t[PD * HD];

// ----------------------------- helpers -------------------------------------
__device__ __forceinline__ uint32_t smem_u32(const void* p) {
    uint32_t a;
    asm("{ .reg .u64 t; cvta.to.shared.u64 t, %1; cvt.u32.u64 %0, t; }"
        : "=r"(a) : "l"(p));
    return a;
}

#define SWZ128(o) ((uint32_t)(o) ^ ((((uint32_t)(o)) >> 3) & 0x70u))

__device__ __forceinline__ void cp16(uint32_t dst, const void* src) {
    asm volatile("cp.async.cg.shared.global [%0], [%1], 16;"
                 :: "r"(dst), "l"(src) : "memory");
}
__device__ __forceinline__ void ldsm_x4(uint32_t* r, uint32_t addr) {
    asm volatile("ldmatrix.sync.aligned.m8n8.x4.shared.b16 {%0,%1,%2,%3}, [%4];"
                 : "=r"(r[0]), "=r"(r[1]), "=r"(r[2]), "=r"(r[3]) : "r"(addr));
}
__device__ __forceinline__ void mma16816(float* c, const uint32_t* a,
                                         uint32_t b0, uint32_t b1) {
    asm volatile(
        "mma.sync.aligned.m16n8k16.row.col.f32.f16.f16.f32 "
        "{%0,%1,%2,%3}, {%4,%5,%6,%7}, {%8,%9}, {%0,%1,%2,%3};"
        : "+f"(c[0]), "+f"(c[1]), "+f"(c[2]), "+f"(c[3])
        : "r"(a[0]), "r"(a[1]), "r"(a[2]), "r"(a[3]), "r"(b0), "r"(b1));
}
// f16-accumulate variant (probe: possibly rt=8 vs 16 for f32-acc)
__device__ __forceinline__ void mma16816h(uint32_t* c, const uint32_t* a,
                                          uint32_t b0, uint32_t b1) {
    asm volatile(
        "mma.sync.aligned.m16n8k16.row.col.f16.f16.f16.f16 "
        "{%0,%1}, {%2,%3,%4,%5}, {%6,%7}, {%0,%1};"
        : "+r"(c[0]), "+r"(c[1])
        : "r"(a[0]), "r"(a[1]), "r"(a[2]), "r"(a[3]), "r"(b0), "r"(b1));
}

// =================== enc GEMM: f32-acc, BM=128 BN=256 ======================
// C[M,N] = act(A[M,K] @ B^T + bias). 256 thr, 8 warps (2M x 4N), warp 64x64.
// MODE: 0 = relu -> fp16 out (ld 2048)
//       1 = none -> f32 ml (ld 512) + fp16 mu (cols < 256, ld 256)
template<int MODE>
__global__ void __launch_bounds__(256, 1)
gemm_mma(const __half* __restrict__ A, const __half* __restrict__ B,
         const float* __restrict__ bias,
         float* __restrict__ outf, __half* __restrict__ oh,
         int Kd, int ldA)
{
    extern __shared__ char smem[];
    const uint32_t sbase = smem_u32(smem);
    constexpr uint32_t STG = 49152;

    const int tid  = threadIdx.x;
    const int lane = tid & 31, wid = tid >> 5;
    const int wm = (wid >> 2) * 64;
    const int wn = (wid & 3) * 64;
    const int m0 = blockIdx.y * 128;
    const int n0 = blockIdx.x * 256;
    const int nk = Kd >> 6;

    const __half* Ag = A + (size_t)m0 * ldA;
    const __half* Bg = B + (size_t)n0 * Kd;

    auto load_stage = [&](int kc) {
        const uint32_t sA = sbase + (uint32_t)(kc % 3) * STG;
        const uint32_t sB = sA + 16384;
        const __half* ga = Ag + kc * 64;
        const __half* gb = Bg + kc * 64;
        #pragma unroll
        for (int i = 0; i < 4; i++) {
            const int u = tid + i * 256;
            const int row = u >> 3, c = u & 7;
            cp16(sA + SWZ128(row * 128 + c * 16), ga + (size_t)row * ldA + c * 8);
        }
        #pragma unroll
        for (int i = 0; i < 8; i++) {
            const int u = tid + i * 256;
            const int row = u >> 3, c = u & 7;
            cp16(sB + SWZ128(row * 128 + c * 16), gb + (size_t)row * Kd + c * 8);
        }
        asm volatile("cp.async.commit_group;" ::: "memory");
    };

    float acc[4][8][4];
    #pragma unroll
    for (int i = 0; i < 4; i++)
        #pragma unroll
        for (int j = 0; j < 8; j++)
            #pragma unroll
            for (int k = 0; k < 4; k++) acc[i][j][k] = 0.0f;

    load_stage(0);
    load_stage(1);

    const int r  = lane & 15;
    const int ch = lane >> 4;

    for (int kc = 0; kc < nk; kc++) {
        if (kc + 1 < nk) asm volatile("cp.async.wait_group 1;" ::: "memory");
        else             asm volatile("cp.async.wait_group 0;" ::: "memory");
        __syncthreads();
        const uint32_t sA = sbase + (uint32_t)(kc % 3) * STG;
        const uint32_t sB = sA + 16384;

        #pragma unroll
        for (int ks = 0; ks < 4; ks++) {
            const int c = ks * 2 + ch;
            uint32_t a[4][4], b[4][4];
            #pragma unroll
            for (int mi = 0; mi < 4; mi++)
                ldsm_x4(a[mi], sA + SWZ128((wm + mi * 16 + r) * 128 + c * 16));
            #pragma unroll
            for (int g = 0; g < 4; g++)
                ldsm_x4(b[g], sB + SWZ128((wn + g * 16 + r) * 128 + c * 16));
            #pragma unroll
            for (int mi = 0; mi < 4; mi++)
                #pragma unroll
                for (int ni = 0; ni < 8; ni++)
                    mma16816(acc[mi][ni], a[mi],
                             b[ni >> 1][ni & 1], b[ni >> 1][2 + (ni & 1)]);
        }
        if (kc + 2 < nk) load_stage(kc + 2);
    }

    const int row0 = lane >> 2;
    const int col0 = (lane & 3) * 2;
    #pragma unroll
    for (int mi = 0; mi < 4; mi++) {
        #pragma unroll
        for (int ni = 0; ni < 8; ni++) {
            const int gc = n0 + wn + ni * 8 + col0;
            const float b0 = __ldg(bias + gc);
            const float b1 = __ldg(bias + gc + 1);
            #pragma unroll
            for (int h = 0; h < 2; h++) {
                const int gr = m0 + wm + mi * 16 + row0 + h * 8;
                float v0 = acc[mi][ni][h * 2 + 0] + b0;
                float v1 = acc[mi][ni][h * 2 + 1] + b1;
                if (MODE == 0) {
                    v0 = fmaxf(v0, 0.0f); v1 = fmaxf(v1, 0.0f);
                    *reinterpret_cast<__half2*>(oh + (size_t)gr * 2048 + gc) =
                        __floats2half2_rn(v0, v1);
                } else {
                    outf[(size_t)gr * 512 + gc]     = v0;
                    outf[(size_t)gr * 512 + gc + 1] = v1;
                    if (gc < 256)
                        *reinterpret_cast<__half2*>(oh + (size_t)gr * 256 + gc) =
                            __floats2half2_rn(v0, v1);
                }
            }
        }
    }
}

// ============= dec GEMM: f16-acc probe, BM=128 BN=128, warp 64x32 ===========
// Per-BK promotion of f16 accumulators into f32 master accumulators.
// MODE: 0 = relu -> fp16 out (ld 2048); 3 = sigmoid -> unpatchify scatter.
template<int MODE>
__global__ void __launch_bounds__(256, 1)
gemm_mma_h(const __half* __restrict__ A, const __half* __restrict__ B,
           const float* __restrict__ bias,
           float* __restrict__ outf, __half* __restrict__ oh,
           int Kd, int ldA)
{
    extern __shared__ char smem[];
    const uint32_t sbase = smem_u32(smem);
    constexpr uint32_t STG = 32768;         // 16KB A + 16KB B

    const int tid  = threadIdx.x;
    const int lane = tid & 31, wid = tid >> 5;
    const int wm = (wid >> 2) * 64;
    const int wn = (wid & 3) * 32;
    const int m0 = blockIdx.y * 128;
    const int n0 = blockIdx.x * 128;
    const int nk = Kd >> 6;

    const __half* Ag = A + (size_t)m0 * ldA;
    const __half* Bg = B + (size_t)n0 * Kd;

    auto load_stage = [&](int kc) {
        const uint32_t sA = sbase + (uint32_t)(kc % 3) * STG;
        const uint32_t sB = sA + 16384;
        const __half* ga = Ag + kc * 64;
        const __half* gb = Bg + kc * 64;
        #pragma unroll
        for (int i = 0; i < 4; i++) {
            const int u = tid + i * 256;
            const int row = u >> 3, c = u & 7;
            cp16(sA + SWZ128(row * 128 + c * 16), ga + (size_t)row * ldA + c * 8);
        }
        #pragma unroll
        for (int i = 0; i < 4; i++) {
            const int u = tid + i * 256;
            const int row = u >> 3, c = u & 7;
            cp16(sB + SWZ128(row * 128 + c * 16), gb + (size_t)row * Kd + c * 8);
        }
        asm volatile("cp.async.commit_group;" ::: "memory");
    };

    float acc[4][4][4];
    #pragma unroll
    for (int i = 0; i < 4; i++)
        #pragma unroll
        for (int j = 0; j < 4; j++)
            #pragma unroll
            for (int k = 0; k < 4; k++) acc[i][j][k] = 0.0f;

    load_stage(0);
    load_stage(1);

    const int r  = lane & 15;
    const int ch = lane >> 4;

    for (int kc = 0; kc < nk; kc++) {
        if (kc + 1 < nk) asm volatile("cp.async.wait_group 1;" ::: "memory");
        else             asm volatile("cp.async.wait_group 0;" ::: "memory");
        __syncthreads();
        const uint32_t sA = sbase + (uint32_t)(kc % 3) * STG;
        const uint32_t sB = sA + 16384;

        uint32_t hacc[4][4][2];               // f16 accumulators for this BK
        #pragma unroll
        for (int i = 0; i < 4; i++)
            #pragma unroll
            for (int j = 0; j < 4; j++)
                hacc[i][j][0] = hacc[i][j][1] = 0u;

        #pragma unroll
        for (int ks = 0; ks < 4; ks++) {
            const int c = ks * 2 + ch;
            uint32_t a[4][4], b[2][4];
            #pragma unroll
            for (int mi = 0; mi < 4; mi++)
                ldsm_x4(a[mi], sA + SWZ128((wm + mi * 16 + r) * 128 + c * 16));
            #pragma unroll
            for (int g = 0; g < 2; g++)
                ldsm_x4(b[g], sB + SWZ128((wn + g * 16 + r) * 128 + c * 16));
            #pragma unroll
            for (int mi = 0; mi < 4; mi++)
                #pragma unroll
                for (int ni = 0; ni < 4; ni++)
                    mma16816h(hacc[mi][ni], a[mi],
                              b[ni >> 1][ni & 1], b[ni >> 1][2 + (ni & 1)]);
        }

        // promote chunk sums to f32 masters
        #pragma unroll
        for (int mi = 0; mi < 4; mi++)
            #pragma unroll
            for (int ni = 0; ni < 4; ni++) {
                const float2 f0 =
                    __half22float2(*reinterpret_cast<__half2*>(&hacc[mi][ni][0]));
                const float2 f1 =
                    __half22float2(*reinterpret_cast<__half2*>(&hacc[mi][ni][1]));
                acc[mi][ni][0] += f0.x; acc[mi][ni][1] += f0.y;
                acc[mi][ni][2] += f1.x; acc[mi][ni][3] += f1.y;
            }

        if (kc + 2 < nk) load_stage(kc + 2);
    }

    const int row0 = lane >> 2;
    const int col0 = (lane & 3) * 2;
    #pragma unroll
    for (int mi = 0; mi < 4; mi++) {
        #pragma unroll
        for (int ni = 0; ni < 4; ni++) {
            const int gc = n0 + wn + ni * 8 + col0;
            const float b0 = __ldg(bias + gc);
            const float b1 = __ldg(bias + gc + 1);
            #pragma unroll
            for (int h = 0; h < 2; h++) {
                const int gr = m0 + wm + mi * 16 + row0 + h * 8;
                float v0 = acc[mi][ni][h * 2 + 0] + b0;
                float v1 = acc[mi][ni][h * 2 + 1] + b1;
                if (MODE == 0) {
                    v0 = fmaxf(v0, 0.0f); v1 = fmaxf(v1, 0.0f);
                    *reinterpret_cast<__half2*>(oh + (size_t)gr * 2048 + gc) =
                        __floats2half2_rn(v0, v1);
                } else {
                    v0 = 1.0f / (1.0f + __expf(-v0));
                    v1 = 1.0f / (1.0f + __expf(-v1));
                    const int b  = gr >> 6, g = gr & 63;
                    const int gh = g >> 3, gw = g & 7;
                    const int cc = gc >> 8, kh = (gc >> 4) & 15, kw = gc & 15;
                    const size_t idx =
                        ((size_t)(b * 3 + cc) * 128 + gh * 16 + kh) * 128 + gw * 16 + kw;
                    *reinterpret_cast<float2*>(outf + idx) = make_float2(v0, v1);
                }
            }
        }
    }
}

// ------------------------------ prep kernels --------------------------------
__global__ void patchify_kernel(const float* __restrict__ x,
                                __half* __restrict__ p, int n)
{
    int i = blockIdx.x * blockDim.x + threadIdx.x;
    if (i >= n) return;
    const int kw    = i & 15;
    const int kh    = (i >> 4) & 15;
    const int c     = (i >> 8) % 3;
    const int token = i / PD;
    const int gw = token & 7;
    const int gh = (token >> 3) & 7;
    const int b  = token >> 6;
    const size_t src = ((size_t)(b * 3 + c) * 128 + gh * 16 + kh) * 128 + gw * 16 + kw;
    p[i] = __float2half_rn(x[src]);
}

__global__ void wT_kernel(const float* __restrict__ w, int Kd, int Nd,
                          __half* __restrict__ t)
{
    __shared__ float tile[32][33];
    const int x = blockIdx.x * 32 + threadIdx.x;
    const int y = blockIdx.y * 32 + threadIdx.y;
    #pragma unroll
    for (int i = 0; i < 32; i += 8)
        tile[threadIdx.y + i][threadIdx.x] = w[(size_t)(y + i) * Nd + x];
    __syncthreads();
    const int n = blockIdx.x * 32 + threadIdx.y;
    const int k = blockIdx.y * 32 + threadIdx.x;
    #pragma unroll
    for (int i = 0; i < 32; i += 8)
        t[(size_t)(n + i) * Kd + k] = __float2half_rn(tile[threadIdx.x][threadIdx.y + i]);
}

__global__ void transpose_ml_tiled(const float* __restrict__ ml,
                                   float* __restrict__ out2)
{
    __shared__ float tile[32][33];
    const int b  = blockIdx.z;
    const int l0 = blockIdx.x * 32;
    const int g0 = blockIdx.y * 32;
    #pragma unroll
    for (int i = 0; i < 32; i += 8) {
        const int g = g0 + threadIdx.y + i;
        tile[threadIdx.y + i][threadIdx.x] =
            ml[(size_t)(b * 64 + g) * L2D + l0 + threadIdx.x];
    }
    __syncthreads();
    #pragma unroll
    for (int i = 0; i < 32; i += 8) {
        const int l = l0 + threadIdx.y + i;
        out2[(size_t)b * (L2D * 64) + (size_t)l * 64 + g0 + threadIdx.x] =
            tile[threadIdx.x][threadIdx.y + i];
    }
}

// ------------------------------- launcher -----------------------------------
extern "C" void kernel_launch(void* const* d_in, const int* in_sizes, int n_in,
                              void* d_out, int out_size)
{
    const float* x      = (const float*)d_in[0];
    const float* w_enc1 = (const float*)d_in[1];
    const float* b_enc1 = (const float*)d_in[2];
    const float* w_enc2 = (const float*)d_in[3];
    const float* b_enc2 = (const float*)d_in[4];
    const float* w_dec1 = (const float*)d_in[5];
    const float* b_dec1 = (const float*)d_in[6];
    const float* w_dec2 = (const float*)d_in[7];
    const float* b_dec2 = (const float*)d_in[8];

    __half *p, *he, *mu, *hd, *w1t, *w2t, *w3t, *w4t;
    float* ml;
    cudaGetSymbolAddress((void**)&p,   g_p);
    cudaGetSymbolAddress((void**)&he,  g_he);
    cudaGetSymbolAddress((void**)&ml,  g_ml);
    cudaGetSymbolAddress((void**)&mu,  g_mu);
    cudaGetSymbolAddress((void**)&hd,  g_hd);
    cudaGetSymbolAddress((void**)&w1t, g_w1t);
    cudaGetSymbolAddress((void**)&w2t, g_w2t);
    cudaGetSymbolAddress((void**)&w3t, g_w3t);
    cudaGetSymbolAddress((void**)&w4t, g_w4t);

    float* out   = (float*)d_out;
    float* recon = out;
    float* ml2d  = out + (size_t)256 * 3 * 128 * 128;

    const int SMEM_E = 3 * 49152;   // 144 KB (enc)
    const int SMEM_D = 3 * 32768;   // 96 KB  (dec)
    cudaFuncSetAttribute(gemm_mma<0>,   cudaFuncAttributeMaxDynamicSharedMemorySize, SMEM_E);
    cudaFuncSetAttribute(gemm_mma<1>,   cudaFuncAttributeMaxDynamicSharedMemorySize, SMEM_E);
    cudaFuncSetAttribute(gemm_mma_h<0>, cudaFuncAttributeMaxDynamicSharedMemorySize, SMEM_D);
    cudaFuncSetAttribute(gemm_mma_h<3>, cudaFuncAttributeMaxDynamicSharedMemorySize, SMEM_D);

    const int n_img = 256 * 3 * 128 * 128;

    // 1) patchify -> fp16
    patchify_kernel<<<(n_img + 255) / 256, 256>>>(x, p, n_img);

    // 2) weight transposes -> fp16 [N,K]
    dim3 tb32(32, 8);
    wT_kernel<<<dim3(HD / 32,   PD / 32),   tb32>>>(w_enc1, PD,   HD,  w1t);
    wT_kernel<<<dim3(L2D / 32,  HD / 32),   tb32>>>(w_enc2, HD,   L2D, w2t);
    wT_kernel<<<dim3(HD / 32,   LDIM / 32), tb32>>>(w_dec1, LDIM, HD,  w3t);
    wT_kernel<<<dim3(PD / 32,   HD / 32),   tb32>>>(w_dec2, HD,   PD,  w4t);

    // 3) enc1: he = relu(p @ w1 + b1)     [16384,768] x [768,2048]  (f32 acc)
    gemm_mma<0><<<dim3(HD / 256, TOK / 128), 256, SMEM_E>>>(
        p, w1t, b_enc1, nullptr, he, PD, PD);

    // 4) enc2: ml = he @ w2 + b2          [16384,2048] x [2048,512] (f32 acc)
    gemm_mma<1><<<dim3(L2D / 256, TOK / 128), 256, SMEM_E>>>(
        he, w2t, b_enc2, ml, mu, HD, HD);

    // 5) mu_logvar_2d output
    transpose_ml_tiled<<<dim3(L2D / 32, 2, 256), tb32>>>(ml, ml2d);

    // 6) dec1: hd = relu(mu @ w3 + b3)    [16384,256] x [256,2048]  (f16 acc)
    gemm_mma_h<0><<<dim3(HD / 128, TOK / 128), 256, SMEM_D>>>(
        mu, w3t, b_dec1, nullptr, hd, LDIM, LDIM);

    // 7) dec2: recon = sigmoid(hd @ w4 + b4), fused scatter         (f16 acc)
    gemm_mma_h<3><<<dim3(PD / 128, TOK / 128), 256, SMEM_D>>>(
        hd, w4t, b_dec2, recon, nullptr, HD, HD);
}

// round 11
// speedup vs baseline: 1.0916x; 1.0916x over previous
#include <cuda_runtime.h>
#include <cuda_fp16.h>
#include <cstdint>
#include <cstddef>

// ---------------------------------------------------------------------------
// ConvVAE2d via mma.sync fp16 GEMMs (baseline sm_103 PTX: cp.async + ldmatrix
// + mma.sync.m16n8k16; tcgen05 unavailable on this toolchain target).
// R11: all GEMMs f32-acc (R9 showed f16-acc is same rate). Occupancy probe:
// 512 threads/CTA (16 warps, 4 per SMSP), warp tile 64x32, BM=128 BN=256.
// ---------------------------------------------------------------------------

#define TOK 16384
#define PD  768
#define HD  2048
#define L2D 512
#define LDIM 256

// ----------------------------- scratch -------------------------------------
__device__ __align__(256) __half g_p[TOK * PD];
__device__ __align__(256) __half g_he[TOK * HD];
__device__ __align__(256) float  g_ml[TOK * L2D];
__device__ __align__(256) __half g_mu[TOK * LDIM];
__device__ __align__(256) __half g_hd[TOK * HD];
__device__ __align__(256) __half g_w1t[HD * PD];
__device__ __align__(256) __half g_w2t[L2D * HD];
__device__ __align__(256) __half g_w3t[HD * LDIM];
__device__ __align__(256) __half g_w4t[PD * HD];

// ----------------------------- helpers -------------------------------------
__device__ __forceinline__ uint32_t smem_u32(const void* p) {
    uint32_t a;
    asm("{ .reg .u64 t; cvta.to.shared.u64 t, %1; cvt.u32.u64 %0, t; }"
        : "=r"(a) : "l"(p));
    return a;
}

#define SWZ128(o) ((uint32_t)(o) ^ ((((uint32_t)(o)) >> 3) & 0x70u))

__device__ __forceinline__ void cp16(uint32_t dst, const void* src) {
    asm volatile("cp.async.cg.shared.global [%0], [%1], 16;"
                 :: "r"(dst), "l"(src) : "memory");
}
__device__ __forceinline__ void ldsm_x4(uint32_t* r, uint32_t addr) {
    asm volatile("ldmatrix.sync.aligned.m8n8.x4.shared.b16 {%0,%1,%2,%3}, [%4];"
                 : "=r"(r[0]), "=r"(r[1]), "=r"(r[2]), "=r"(r[3]) : "r"(addr));
}
__device__ __forceinline__ void mma16816(float* c, const uint32_t* a,
                                         uint32_t b0, uint32_t b1) {
    asm volatile(
        "mma.sync.aligned.m16n8k16.row.col.f32.f16.f16.f32 "
        "{%0,%1,%2,%3}, {%4,%5,%6,%7}, {%8,%9}, {%0,%1,%2,%3};"
        : "+f"(c[0]), "+f"(c[1]), "+f"(c[2]), "+f"(c[3])
        : "r"(a[0]), "r"(a[1]), "r"(a[2]), "r"(a[3]), "r"(b0), "r"(b1));
}

// ------------------------------- GEMM kernel --------------------------------
// C[M,N] = act(A[M,K] @ B^T + bias).  A:[M,K] fp16 K-contig. B:[N,K] fp16
// (= W^T) K-contig.  BM=128, BN=256, BK=64, 512 thr, 16 warps (2M x 8N),
// warp tile 64x32, 3-stage cp.async pipeline, SW128 smem.
// MODE: 0 = relu -> fp16 out (ld 2048)
//       1 = none -> f32 ml (ld 512) + fp16 mu (cols < 256, ld 256)
//       3 = sigmoid -> fused unpatchify scatter to recon (f32)
template<int MODE>
__global__ void __launch_bounds__(512, 1)
gemm_mma(const __half* __restrict__ A, const __half* __restrict__ B,
         const float* __restrict__ bias,
         float* __restrict__ outf, __half* __restrict__ oh,
         int Kd, int ldA)
{
    extern __shared__ char smem[];
    const uint32_t sbase = smem_u32(smem);
    constexpr uint32_t STG = 49152;         // 16KB A + 32KB B per stage

    const int tid  = threadIdx.x;
    const int lane = tid & 31, wid = tid >> 5;
    const int wm = (wid >> 3) * 64;         // warp M offset (0/64)
    const int wn = (wid & 7) * 32;          // warp N offset (0..224)
    const int m0 = blockIdx.y * 128;
    const int n0 = blockIdx.x * 256;
    const int nk = Kd >> 6;

    const __half* Ag = A + (size_t)m0 * ldA;
    const __half* Bg = B + (size_t)n0 * Kd;

    auto load_stage = [&](int kc) {
        const uint32_t sA = sbase + (uint32_t)(kc % 3) * STG;
        const uint32_t sB = sA + 16384;
        const __half* ga = Ag + kc * 64;
        const __half* gb = Bg + kc * 64;
        #pragma unroll
        for (int i = 0; i < 2; i++) {           // A: 128 rows x 128B
            const int u = tid + i * 512;
            const int row = u >> 3, c = u & 7;
            cp16(sA + SWZ128(row * 128 + c * 16), ga + (size_t)row * ldA + c * 8);
        }
        #pragma unroll
        for (int i = 0; i < 4; i++) {           // B: 256 rows x 128B
            const int u = tid + i * 512;
            const int row = u >> 3, c = u & 7;
            cp16(sB + SWZ128(row * 128 + c * 16), gb + (size_t)row * Kd + c * 8);
        }
        asm volatile("cp.async.commit_group;" ::: "memory");
    };

    float acc[4][4][4];
    #pragma unroll
    for (int i = 0; i < 4; i++)
        #pragma unroll
        for (int j = 0; j < 4; j++)
            #pragma unroll
            for (int k = 0; k < 4; k++) acc[i][j][k] = 0.0f;

    load_stage(0);
    load_stage(1);

    const int r  = lane & 15;
    const int ch = lane >> 4;

    for (int kc = 0; kc < nk; kc++) {
        if (kc + 1 < nk) asm volatile("cp.async.wait_group 1;" ::: "memory");
        else             asm volatile("cp.async.wait_group 0;" ::: "memory");
        __syncthreads();
        const uint32_t sA = sbase + (uint32_t)(kc % 3) * STG;
        const uint32_t sB = sA + 16384;

        #pragma unroll
        for (int ks = 0; ks < 4; ks++) {        // 4 x k16 per BK=64
            const int c = ks * 2 + ch;          // 16B chunk index
            uint32_t a[4][4], b[2][4];
            #pragma unroll
            for (int mi = 0; mi < 4; mi++)
                ldsm_x4(a[mi], sA + SWZ128((wm + mi * 16 + r) * 128 + c * 16));
            #pragma unroll
            for (int g = 0; g < 2; g++)
                ldsm_x4(b[g], sB + SWZ128((wn + g * 16 + r) * 128 + c * 16));
            #pragma unroll
            for (int mi = 0; mi < 4; mi++)
                #pragma unroll
                for (int ni = 0; ni < 4; ni++)
                    mma16816(acc[mi][ni], a[mi],
                             b[ni >> 1][ni & 1], b[ni >> 1][2 + (ni & 1)]);
        }
        if (kc + 2 < nk) load_stage(kc + 2);
    }

    // ------------------------------ epilogue --------------------------------
    const int row0 = lane >> 2;
    const int col0 = (lane & 3) * 2;
    #pragma unroll
    for (int mi = 0; mi < 4; mi++) {
        #pragma unroll
        for (int ni = 0; ni < 4; ni++) {
            const int gc = n0 + wn + ni * 8 + col0;
            const float b0 = __ldg(bias + gc);
            const float b1 = __ldg(bias + gc + 1);
            #pragma unroll
            for (int h = 0; h < 2; h++) {
                const int gr = m0 + wm + mi * 16 + row0 + h * 8;
                float v0 = acc[mi][ni][h * 2 + 0] + b0;
                float v1 = acc[mi][ni][h * 2 + 1] + b1;
                if (MODE == 0) {
                    v0 = fmaxf(v0, 0.0f); v1 = fmaxf(v1, 0.0f);
                    *reinterpret_cast<__half2*>(oh + (size_t)gr * 2048 + gc) =
                        __floats2half2_rn(v0, v1);
                } else if (MODE == 1) {
                    outf[(size_t)gr * 512 + gc]     = v0;
                    outf[(size_t)gr * 512 + gc + 1] = v1;
                    if (gc < 256)
                        *reinterpret_cast<__half2*>(oh + (size_t)gr * 256 + gc) =
                            __floats2half2_rn(v0, v1);
                } else {
                    v0 = 1.0f / (1.0f + __expf(-v0));
                    v1 = 1.0f / (1.0f + __expf(-v1));
                    // fused unpatchify: gr = token, gc = c*256 + kh*16 + kw
                    const int b  = gr >> 6, g = gr & 63;
                    const int gh = g >> 3, gw = g & 7;
                    const int cc = gc >> 8, kh = (gc >> 4) & 15, kw = gc & 15;
                    const size_t idx =
                        ((size_t)(b * 3 + cc) * 128 + gh * 16 + kh) * 128 + gw * 16 + kw;
                    *reinterpret_cast<float2*>(outf + idx) = make_float2(v0, v1);
                }
            }
        }
    }
}

// ------------------------------ prep kernels --------------------------------
__global__ void patchify_kernel(const float* __restrict__ x,
                                __half* __restrict__ p, int n)
{
    int i = blockIdx.x * blockDim.x + threadIdx.x;
    if (i >= n) return;
    const int kw    = i & 15;
    const int kh    = (i >> 4) & 15;
    const int c     = (i >> 8) % 3;
    const int token = i / PD;
    const int gw = token & 7;
    const int gh = (token >> 3) & 7;
    const int b  = token >> 6;
    const size_t src = ((size_t)(b * 3 + c) * 128 + gh * 16 + kh) * 128 + gw * 16 + kw;
    p[i] = __float2half_rn(x[src]);
}

// t[n,k] = w[k,n]  (fp32 -> fp16 transpose). blockDim (32,8).
__global__ void wT_kernel(const float* __restrict__ w, int Kd, int Nd,
                          __half* __restrict__ t)
{
    __shared__ float tile[32][33];
    const int x = blockIdx.x * 32 + threadIdx.x;   // n
    const int y = blockIdx.y * 32 + threadIdx.y;   // k
    #pragma unroll
    for (int i = 0; i < 32; i += 8)
        tile[threadIdx.y + i][threadIdx.x] = w[(size_t)(y + i) * Nd + x];
    __syncthreads();
    const int n = blockIdx.x * 32 + threadIdx.y;
    const int k = blockIdx.y * 32 + threadIdx.x;
    #pragma unroll
    for (int i = 0; i < 32; i += 8)
        t[(size_t)(n + i) * Kd + k] = __float2half_rn(tile[threadIdx.x][threadIdx.y + i]);
}

// out2[b, l, g] = ml[b*64+g, l] — smem-tiled: both sides coalesced.
__global__ void transpose_ml_tiled(const float* __restrict__ ml,
                                   float* __restrict__ out2)
{
    __shared__ float tile[32][33];
    const int b  = blockIdx.z;
    const int l0 = blockIdx.x * 32;
    const int g0 = blockIdx.y * 32;
    #pragma unroll
    for (int i = 0; i < 32; i += 8) {
        const int g = g0 + threadIdx.y + i;
        tile[threadIdx.y + i][threadIdx.x] =
            ml[(size_t)(b * 64 + g) * L2D + l0 + threadIdx.x];
    }
    __syncthreads();
    #pragma unroll
    for (int i = 0; i < 32; i += 8) {
        const int l = l0 + threadIdx.y + i;
        out2[(size_t)b * (L2D * 64) + (size_t)l * 64 + g0 + threadIdx.x] =
            tile[threadIdx.x][threadIdx.y + i];
    }
}

// ------------------------------- launcher -----------------------------------
extern "C" void kernel_launch(void* const* d_in, const int* in_sizes, int n_in,
                              void* d_out, int out_size)
{
    const float* x      = (const float*)d_in[0];
    const float* w_enc1 = (const float*)d_in[1];
    const float* b_enc1 = (const float*)d_in[2];
    const float* w_enc2 = (const float*)d_in[3];
    const float* b_enc2 = (const float*)d_in[4];
    const float* w_dec1 = (const float*)d_in[5];
    const float* b_dec1 = (const float*)d_in[6];
    const float* w_dec2 = (const float*)d_in[7];
    const float* b_dec2 = (const float*)d_in[8];

    __half *p, *he, *mu, *hd, *w1t, *w2t, *w3t, *w4t;
    float* ml;
    cudaGetSymbolAddress((void**)&p,   g_p);
    cudaGetSymbolAddress((void**)&he,  g_he);
    cudaGetSymbolAddress((void**)&ml,  g_ml);
    cudaGetSymbolAddress((void**)&mu,  g_mu);
    cudaGetSymbolAddress((void**)&hd,  g_hd);
    cudaGetSymbolAddress((void**)&w1t, g_w1t);
    cudaGetSymbolAddress((void**)&w2t, g_w2t);
    cudaGetSymbolAddress((void**)&w3t, g_w3t);
    cudaGetSymbolAddress((void**)&w4t, g_w4t);

    float* out   = (float*)d_out;
    float* recon = out;
    float* ml2d  = out + (size_t)256 * 3 * 128 * 128;

    const int SMEM = 3 * 49152;   // 144 KB
    cudaFuncSetAttribute(gemm_mma<0>, cudaFuncAttributeMaxDynamicSharedMemorySize, SMEM);
    cudaFuncSetAttribute(gemm_mma<1>, cudaFuncAttributeMaxDynamicSharedMemorySize, SMEM);
    cudaFuncSetAttribute(gemm_mma<3>, cudaFuncAttributeMaxDynamicSharedMemorySize, SMEM);

    const int n_img = 256 * 3 * 128 * 128;   // 12,582,912

    // 1) patchify -> fp16
    patchify_kernel<<<(n_img + 255) / 256, 256>>>(x, p, n_img);

    // 2) weight transposes -> fp16 [N,K]
    dim3 tb32(32, 8);
    wT_kernel<<<dim3(HD / 32,   PD / 32),   tb32>>>(w_enc1, PD,   HD,  w1t);
    wT_kernel<<<dim3(L2D / 32,  HD / 32),   tb32>>>(w_enc2, HD,   L2D, w2t);
    wT_kernel<<<dim3(HD / 32,   LDIM / 32), tb32>>>(w_dec1, LDIM, HD,  w3t);
    wT_kernel<<<dim3(PD / 32,   HD / 32),   tb32>>>(w_dec2, HD,   PD,  w4t);

    // 3) enc1: he = relu(p @ w1 + b1)     [16384,768] x [768,2048]
    gemm_mma<0><<<dim3(HD / 256, TOK / 128), 512, SMEM>>>(
        p, w1t, b_enc1, nullptr, he, PD, PD);

    // 4) enc2: ml = he @ w2 + b2          [16384,2048] x [2048,512]
    gemm_mma<1><<<dim3(L2D / 256, TOK / 128), 512, SMEM>>>(
        he, w2t, b_enc2, ml, mu, HD, HD);

    // 5) mu_logvar_2d output (tiled transpose)
    transpose_ml_tiled<<<dim3(L2D / 32, 2, 256), tb32>>>(ml, ml2d);

    // 6) dec1: hd = relu(mu @ w3 + b3)    [16384,256] x [256,2048]
    gemm_mma<0><<<dim3(HD / 256, TOK / 128), 512, SMEM>>>(
        mu, w3t, b_dec1, nullptr, hd, LDIM, LDIM);

    // 7) dec2: recon = sigmoid(hd @ w4 + b4), fused unpatchify scatter
    gemm_mma<3><<<dim3(PD / 256, TOK / 128), 512, SMEM>>>(
        hd, w4t, b_dec2, recon, nullptr, HD, HD);
}